// round 3
// baseline (speedup 1.0000x reference)
#include <cuda_runtime.h>
#include <cstdint>

// Problem constants (fixed by the reference):
//   R_MAX=32, S_MAX=2, C_Z=128, IN_FEATS=139
#define C_Z      128
#define IN_FEATS 139

// Fused table layout (rows of 128 floats):
//   [0,66)    a rows:  Wt[dres]                       (dres in [0,65])
//   [66,132)  b rows:  Wt[66+dtok]                    (dtok in [0,65])
//   [132,138) c rows:  ec<5 ? Wt[132]+Wt[133+ec] : Wt[138]
//   [138,144) bc rows:  b_sent + c_ec      (b_sent = Wt[131])
//   [144,150) abc rows: a_sent + b_sent + c_ec  (a_sent = Wt[65])
#define ROW_A    0
#define ROW_B    66
#define ROW_C    132
#define ROW_BC   138
#define ROW_ABC  144
#define TAB_ROWS 150

#define N_MAX    1024

__device__ float g_tab[TAB_ROWS * C_Z];

// ---------------------------------------------------------------------------
// Pre-kernel: build fused table. W layout: [C_Z, IN_FEATS] row-major,
// Wt[f][c] = W[c*IN_FEATS + f].
// ---------------------------------------------------------------------------
__global__ void build_tables_kernel(const float* __restrict__ W) {
    int r = blockIdx.x;          // 0..149
    int c = threadIdx.x;         // 0..127
    const float* wc = W + (size_t)c * IN_FEATS;

    float a_sent = wc[65];
    float b_sent = wc[131];

    float v;
    if (r < 132) {
        v = wc[r];                       // a rows and b rows
    } else {
        int k = (r - 132) % 6;           // ec class
        float ck = (k < 5) ? (wc[132] + wc[133 + k]) : wc[138];
        if (r < 138)      v = ck;                    // c rows
        else if (r < 144) v = b_sent + ck;           // bc rows
        else              v = a_sent + b_sent + ck;  // abc rows
    }
    g_tab[r * C_Z + c] = v;
}

// ---------------------------------------------------------------------------
// Main kernel: one block per query row i; 256 threads = 8 warps.
// Table lives in L1 (read via __ldg) — no smem staging, only 4KB pk array.
// The 6 abc rows (case ai!=aj, ~75% of pairs) are preloaded into registers.
// pk encoding: r0 | r1<<9 | r2<<18 | case<<27   (case 0=1row, 1=2rows, 2=3rows)
// ---------------------------------------------------------------------------
__global__ __launch_bounds__(256)
void relpos_kernel(const int* __restrict__ asym,
                   const int* __restrict__ resi,
                   const int* __restrict__ ent,
                   const int* __restrict__ sym,
                   const int* __restrict__ tok,
                   float* __restrict__ out,
                   int N) {
    __shared__ unsigned s_pk[N_MAX];

    const int i = blockIdx.x;
    const int ai = asym[i], ri = resi[i], ei = ent[i], si = sym[i], ti = tok[i];

    // ---- phase 1: per-j packed indices (once per block) ----
    for (int j = threadIdx.x; j < N; j += blockDim.x) {
        const int aj = __ldg(asym + j);
        const int rj = __ldg(resi + j);
        const int ej = __ldg(ent  + j);
        const int sj = __ldg(sym  + j);
        const int tj = __ldg(tok  + j);

        int ec = (ei == ej) ? min(max(si - sj + 2, 0), 4) : 5;

        unsigned pk;
        if (ai != aj) {
            pk = (unsigned)ec;                               // case 0: abc[ec]
        } else {
            int dres = min(max(ri - rj + 32, 0), 64);
            if (ri != rj) {
                pk = (unsigned)(ROW_A + dres)
                   | ((unsigned)(ROW_BC + ec) << 9)
                   | (1u << 27);                             // case 1
            } else {
                int dtok = min(max(ti - tj + 32, 0), 64);
                pk = (unsigned)(ROW_A + dres)
                   | ((unsigned)(ROW_B + dtok) << 9)
                   | ((unsigned)(ROW_C + ec)  << 18)
                   | (2u << 27);                             // case 2
            }
        }
        s_pk[j] = pk;
    }
    __syncthreads();

    // ---- phase 2: emit output rows ----
    const int lane = threadIdx.x & 31;
    const int wid  = threadIdx.x >> 5;
    const float4* t4 = (const float4*)g_tab;                 // [TAB_ROWS][32]

    // Preload the 6 fully-fused rows into registers (case 0 -> zero loads).
    const float4 abc0 = __ldg(t4 + (ROW_ABC + 0) * 32 + lane);
    const float4 abc1 = __ldg(t4 + (ROW_ABC + 1) * 32 + lane);
    const float4 abc2 = __ldg(t4 + (ROW_ABC + 2) * 32 + lane);
    const float4 abc3 = __ldg(t4 + (ROW_ABC + 3) * 32 + lane);
    const float4 abc4 = __ldg(t4 + (ROW_ABC + 4) * 32 + lane);
    const float4 abc5 = __ldg(t4 + (ROW_ABC + 5) * 32 + lane);

    float* out_i = out + (size_t)i * N * C_Z;

    #pragma unroll 2
    for (int j = wid; j < N; j += 8) {
        const unsigned pk = s_pk[j];                         // warp-uniform
        float4* dst = (float4*)(out_i + (size_t)j * C_Z) + lane;
        const unsigned cs = pk >> 27;

        if (cs == 0) {
            float4 v;
            switch (pk) {                                    // warp-uniform branch
                case 0:  v = abc0; break;
                case 1:  v = abc1; break;
                case 2:  v = abc2; break;
                case 3:  v = abc3; break;
                case 4:  v = abc4; break;
                default: v = abc5; break;
            }
            __stcs(dst, v);
        } else {
            const int r0 = pk & 511;
            const int r1 = (pk >> 9) & 511;
            float4 v = __ldg(t4 + r0 * 32 + lane);
            const float4 b = __ldg(t4 + r1 * 32 + lane);
            v.x += b.x; v.y += b.y; v.z += b.z; v.w += b.w;
            if (cs == 2) {
                const int r2 = (pk >> 18) & 511;
                const float4 c = __ldg(t4 + r2 * 32 + lane);
                v.x += c.x; v.y += c.y; v.z += c.z; v.w += c.w;
            }
            __stcs(dst, v);
        }
    }
}

extern "C" void kernel_launch(void* const* d_in, const int* in_sizes, int n_in,
                              void* d_out, int out_size) {
    const float* W    = (const float*)d_in[0];
    const int*   asym = (const int*)d_in[1];
    const int*   resi = (const int*)d_in[2];
    const int*   ent  = (const int*)d_in[3];
    const int*   sym  = (const int*)d_in[4];
    const int*   tok  = (const int*)d_in[5];
    float*       out  = (float*)d_out;

    const int N = in_sizes[1];   // 1024

    build_tables_kernel<<<TAB_ROWS, C_Z>>>(W);
    relpos_kernel<<<N, 256>>>(asym, resi, ent, sym, tok, out, N);
}

// round 4
// speedup vs baseline: 1.1296x; 1.1296x over previous
#include <cuda_runtime.h>
#include <cstdint>

// Problem constants: R_MAX=32, S_MAX=2, C_Z=128, IN_FEATS=139
#define C_Z      128
#define IN_FEATS 139

// Global fused table layout (rows of 128 floats):
//   [0,66)    a rows:    Wt[dres]
//   [66,132)  b rows:    Wt[66+dtok]
//   [132,138) c rows:    ec<5 ? Wt[132]+Wt[133+ec] : Wt[138]
//   [138,144) bc rows:   b_sent + c_ec              (b_sent = Wt[131])
//   [144,150) abc rows:  a_sent + b_sent + c_ec     (a_sent = Wt[65])
//   [150,156) a32c rows: a[32] + c_ec               (case ri==rj: dres==32)
//   156       zero row
#define GROW_B    66
#define GTAB_ROWS 157

// Shared-memory table (copied rows; non-a rows are global_row - 72):
//   [0,66) a | [66,72) bc | [72,78) abc | [78,84) a32c | 84 zero
#define S_A     0
#define S_BC    66
#define S_ABC   72
#define S_A32C  78
#define S_ZERO  84
#define S_ROWS  85

#define N_MAX   1024

__device__ float g_tab[GTAB_ROWS * C_Z];

// ---------------------------------------------------------------------------
// Pre-kernel: build fused table. W: [C_Z, IN_FEATS] row-major,
// Wt[f][c] = W[c*IN_FEATS + f].
// ---------------------------------------------------------------------------
__global__ void build_tables_kernel(const float* __restrict__ W) {
    int r = blockIdx.x;          // 0..156
    int c = threadIdx.x;         // 0..127
    const float* wc = W + (size_t)c * IN_FEATS;

    float a_sent = wc[65];
    float b_sent = wc[131];
    float a32    = wc[32];

    float v;
    if (r < 132) {
        v = wc[r];                                   // a rows, b rows
    } else if (r == 156) {
        v = 0.0f;                                    // zero row
    } else {
        int k = (r - 132) % 6;                       // ec class
        float ck = (k < 5) ? (wc[132] + wc[133 + k]) : wc[138];
        if      (r < 138) v = ck;                    // c rows
        else if (r < 144) v = b_sent + ck;           // bc rows
        else if (r < 150) v = a_sent + b_sent + ck;  // abc rows
        else              v = a32 + ck;              // a32c rows
    }
    g_tab[r * C_Z + c] = v;
}

// ---------------------------------------------------------------------------
// Main kernel: one block per query row i; 256 threads = 8 warps.
// Every output row is the sum of exactly two smem table rows (plus a rare
// predicated global b-row for the ri==rj case). Branch-free uniform hot loop.
// pk encoding: r0(7b) | r1(7b)<<7 | has_b<<14 | dtok<<15
// ---------------------------------------------------------------------------
__global__ __launch_bounds__(256)
void relpos_kernel(const int* __restrict__ asym,
                   const int* __restrict__ resi,
                   const int* __restrict__ ent,
                   const int* __restrict__ sym,
                   const int* __restrict__ tok,
                   float* __restrict__ out,
                   int N) {
    extern __shared__ float s_mem[];
    float*    s_tab = s_mem;                                  // 85*128 floats
    unsigned* s_pk  = (unsigned*)(s_mem + S_ROWS * C_Z);      // N entries

    // ---- table copy: gather 85 rows (a rows as-is, others at g_row = s+72) ----
    {
        const float4* src = (const float4*)g_tab;
        float4*       dst = (float4*)s_tab;
        for (int k = threadIdx.x; k < S_ROWS * 32; k += blockDim.x) {
            int s_row = k >> 5;
            int g_row = (s_row < 66) ? s_row : s_row + 72;
            dst[k] = src[g_row * 32 + (k & 31)];
        }
    }

    const int i = blockIdx.x;
    const int ai = asym[i], ri = resi[i], ei = ent[i], si = sym[i], ti = tok[i];

    // ---- phase 1: per-j packed indices (once per block) ----
    for (int j = threadIdx.x; j < N; j += blockDim.x) {
        const int aj = __ldg(asym + j);
        const int rj = __ldg(resi + j);
        const int ej = __ldg(ent  + j);
        const int sj = __ldg(sym  + j);
        const int tj = __ldg(tok  + j);

        int ec = (ei == ej) ? min(max(si - sj + 2, 0), 4) : 5;

        unsigned pk;
        if (ai != aj) {
            pk = (unsigned)(S_ABC + ec) | ((unsigned)S_ZERO << 7);
        } else if (ri != rj) {
            int dres = min(max(ri - rj + 32, 0), 64);
            pk = (unsigned)(S_A + dres) | ((unsigned)(S_BC + ec) << 7);
        } else {
            // dres == 32 exactly; fold a[32] into a32c[ec]; b row from global.
            int dtok = min(max(ti - tj + 32, 0), 64);
            pk = (unsigned)(S_A32C + ec) | ((unsigned)S_ZERO << 7)
               | (1u << 14) | ((unsigned)dtok << 15);
        }
        s_pk[j] = pk;
    }
    __syncthreads();

    // ---- phase 2: uniform 2-row sum per pair; 4 contiguous j's per warp sweep ----
    const int lane = threadIdx.x & 31;
    const int wid  = threadIdx.x >> 5;
    const float4* t4  = (const float4*)s_tab;                 // [85][32]
    const float4* gb4 = (const float4*)(g_tab + GROW_B * C_Z);
    float* out_i = out + (size_t)i * N * C_Z;

    for (int j0 = wid * 4; j0 < N; j0 += 32) {
        #pragma unroll
        for (int u = 0; u < 4; u++) {
            const int j = j0 + u;
            const unsigned pk = s_pk[j];                      // warp-uniform
            const int r0 = pk & 127;
            const int r1 = (pk >> 7) & 127;

            float4 v = t4[r0 * 32 + lane];
            const float4 b = t4[r1 * 32 + lane];
            v.x += b.x; v.y += b.y; v.z += b.z; v.w += b.w;

            if (pk & (1u << 14)) {                            // rare (~3%), warp-uniform
                const int dtok = (int)(pk >> 15);
                const float4 g = __ldg(gb4 + dtok * 32 + lane);
                v.x += g.x; v.y += g.y; v.z += g.z; v.w += g.w;
            }
            __stcs((float4*)(out_i + (size_t)j * C_Z) + lane, v);
        }
    }
}

extern "C" void kernel_launch(void* const* d_in, const int* in_sizes, int n_in,
                              void* d_out, int out_size) {
    const float* W    = (const float*)d_in[0];
    const int*   asym = (const int*)d_in[1];
    const int*   resi = (const int*)d_in[2];
    const int*   ent  = (const int*)d_in[3];
    const int*   sym  = (const int*)d_in[4];
    const int*   tok  = (const int*)d_in[5];
    float*       out  = (float*)d_out;

    const int N = in_sizes[1];   // 1024

    const int smem = S_ROWS * C_Z * (int)sizeof(float) + N_MAX * (int)sizeof(unsigned);
    cudaFuncSetAttribute(relpos_kernel,
                         cudaFuncAttributeMaxDynamicSharedMemorySize, smem);

    build_tables_kernel<<<GTAB_ROWS, C_Z>>>(W);
    relpos_kernel<<<N, 256, smem>>>(asym, resi, ent, sym, tok, out, N);
}

// round 5
// speedup vs baseline: 1.1925x; 1.0557x over previous
#include <cuda_runtime.h>
#include <cstdint>

// Problem constants: R_MAX=32, S_MAX=2, C_Z=128, IN_FEATS=139
#define C_Z      128
#define IN_FEATS 139

// Global fused table layout (rows of 128 floats):
//   [0,66)    a rows:    Wt[dres]
//   [66,132)  b rows:    Wt[66+dtok]
//   [132,138) c rows:    ec<5 ? Wt[132]+Wt[133+ec] : Wt[138]
//   [138,144) bc rows:   b_sent + c_ec              (b_sent = Wt[131])
//   [144,150) abc rows:  a_sent + b_sent + c_ec     (a_sent = Wt[65])
//   [150,156) a32c rows: a[32] + c_ec               (case ri==rj: dres==32)
#define GROW_B    66
#define GTAB_ROWS 156

// Shared-memory table (a rows as-is; fused rows at global_row - 72):
//   [0,66) a | [66,72) bc | [72,78) abc | [78,84) a32c
#define S_A     0
#define S_BC    66
#define S_ABC   72
#define S_A32C  78
#define S_ROWS  84

#define N_MAX   1024

// pk flag bits
#define PK_TWO  (1u << 14)   // add second smem row r1
#define PK_GB   (1u << 15)   // add global b[dtok] row (rare ri==rj case)

__device__ float g_tab[GTAB_ROWS * C_Z];

// ---------------------------------------------------------------------------
// Pre-kernel: build fused table. W: [C_Z, IN_FEATS] row-major,
// Wt[f][c] = W[c*IN_FEATS + f].
// ---------------------------------------------------------------------------
__global__ void build_tables_kernel(const float* __restrict__ W) {
    int r = blockIdx.x;          // 0..155
    int c = threadIdx.x;         // 0..127
    const float* wc = W + (size_t)c * IN_FEATS;

    float a_sent = wc[65];
    float b_sent = wc[131];
    float a32    = wc[32];

    float v;
    if (r < 132) {
        v = wc[r];                                   // a rows, b rows
    } else {
        int k = (r - 132) % 6;                       // ec class
        float ck = (k < 5) ? (wc[132] + wc[133 + k]) : wc[138];
        if      (r < 138) v = ck;                    // c rows
        else if (r < 144) v = b_sent + ck;           // bc rows
        else if (r < 150) v = a_sent + b_sent + ck;  // abc rows
        else              v = a32 + ck;              // a32c rows
    }
    g_tab[r * C_Z + c] = v;
}

// ---------------------------------------------------------------------------
// Main kernel: one block per query row i; 256 threads = 8 warps.
// Hot loop: 1 LDS.128 (75% of pairs) or 2 (25%), warp-uniform predication,
// + STG.128 streaming store. Rare (~3%) extra global b-row.
// pk: r0(7b) | r1(7b)<<7 | TWO<<14 | GB<<15 | dtok<<16
// ---------------------------------------------------------------------------
__global__ __launch_bounds__(256)
void relpos_kernel(const int* __restrict__ asym,
                   const int* __restrict__ resi,
                   const int* __restrict__ ent,
                   const int* __restrict__ sym,
                   const int* __restrict__ tok,
                   float* __restrict__ out,
                   int N) {
    extern __shared__ float s_mem[];
    float*    s_tab = s_mem;                                  // 84*128 floats
    unsigned* s_pk  = (unsigned*)(s_mem + S_ROWS * C_Z);      // N entries

    // ---- table copy: 84 rows (a rows as-is, fused rows at g_row = s+72) ----
    {
        const float4* src = (const float4*)g_tab;
        float4*       dst = (float4*)s_tab;
        for (int k = threadIdx.x; k < S_ROWS * 32; k += blockDim.x) {
            int s_row = k >> 5;
            int g_row = (s_row < 66) ? s_row : s_row + 72;
            dst[k] = src[g_row * 32 + (k & 31)];
        }
    }

    const int i = blockIdx.x;
    const int ai = asym[i], ri = resi[i], ei = ent[i], si = sym[i], ti = tok[i];

    // ---- phase 1: per-j packed indices (once per block) ----
    for (int j = threadIdx.x; j < N; j += blockDim.x) {
        const int aj = __ldg(asym + j);
        const int rj = __ldg(resi + j);
        const int ej = __ldg(ent  + j);
        const int sj = __ldg(sym  + j);
        const int tj = __ldg(tok  + j);

        int ec = (ei == ej) ? min(max(si - sj + 2, 0), 4) : 5;

        unsigned pk;
        if (ai != aj) {
            pk = (unsigned)(S_ABC + ec);                     // 1 row
        } else if (ri != rj) {
            int dres = min(max(ri - rj + 32, 0), 64);
            pk = (unsigned)(S_A + dres)
               | ((unsigned)(S_BC + ec) << 7) | PK_TWO;      // 2 rows
        } else {
            // dres == 32 exactly; a[32] folded into a32c[ec]; b row global.
            int dtok = min(max(ti - tj + 32, 0), 64);
            pk = (unsigned)(S_A32C + ec)
               | PK_GB | ((unsigned)dtok << 16);             // 1 row + global
        }
        s_pk[j] = pk;
    }
    __syncthreads();

    // ---- phase 2: 4 contiguous j's per warp sweep, warp-uniform branches ----
    const int lane = threadIdx.x & 31;
    const int wid  = threadIdx.x >> 5;
    const float4* t4  = (const float4*)s_tab;                 // [84][32]
    const float4* gb4 = (const float4*)(g_tab + GROW_B * C_Z);
    float* out_i = out + (size_t)i * N * C_Z;

    for (int j0 = wid * 4; j0 < N; j0 += 32) {
        #pragma unroll
        for (int u = 0; u < 4; u++) {
            const int j = j0 + u;
            const unsigned pk = s_pk[j];                      // warp-uniform
            const int r0 = pk & 127;

            float4 v = t4[r0 * 32 + lane];

            if (pk & PK_TWO) {                                // ~25%, warp-uniform
                const int r1 = (pk >> 7) & 127;
                const float4 b = t4[r1 * 32 + lane];
                v.x += b.x; v.y += b.y; v.z += b.z; v.w += b.w;
            }
            if (pk & PK_GB) {                                 // ~3%, warp-uniform
                const int dtok = (int)(pk >> 16);
                const float4 g = __ldg(gb4 + dtok * 32 + lane);
                v.x += g.x; v.y += g.y; v.z += g.z; v.w += g.w;
            }
            __stcs((float4*)(out_i + (size_t)j * C_Z) + lane, v);
        }
    }
}

extern "C" void kernel_launch(void* const* d_in, const int* in_sizes, int n_in,
                              void* d_out, int out_size) {
    const float* W    = (const float*)d_in[0];
    const int*   asym = (const int*)d_in[1];
    const int*   resi = (const int*)d_in[2];
    const int*   ent  = (const int*)d_in[3];
    const int*   sym  = (const int*)d_in[4];
    const int*   tok  = (const int*)d_in[5];
    float*       out  = (float*)d_out;

    const int N = in_sizes[1];   // 1024

    const int smem = S_ROWS * C_Z * (int)sizeof(float) + N_MAX * (int)sizeof(unsigned);
    cudaFuncSetAttribute(relpos_kernel,
                         cudaFuncAttributeMaxDynamicSharedMemorySize, smem);

    build_tables_kernel<<<GTAB_ROWS, C_Z>>>(W);
    relpos_kernel<<<N, 256, smem>>>(asym, resi, ent, sym, tok, out, N);
}